// round 14
// baseline (speedup 1.0000x reference)
#include <cuda_runtime.h>
#include <cuda_bf16.h>
#include <cuda_fp16.h>
#include <cuda_fp8.h>
#include <cstdint>

#define DIM 64
#define NCI_MAX 150000
#define FMA_MAX 100000
#define GATHER_BLOCKS 2048
#define GATHER_TPB 256
#define CONV_BLOCKS 512

// ---------------- scratch (device globals: allocation-free rule) ----------------
__device__ __align__(128) unsigned char g_Hn8[NCI_MAX * DIM];   // e4m3, 9.6 MB
__device__ __align__(128) unsigned char g_Hm8[NCI_MAX * DIM];   // e4m3, 9.6 MB
__device__ __align__(128) unsigned char g_Fb8[FMA_MAX * DIM];   // e4m3, 6.4 MB
__device__ float g_Nn[NCI_MAX];       // row norms |Hn_r|^2 (f32-exact)
__device__ float g_Nm[NCI_MAX];
__device__ float g_Nf[FMA_MAX];
__device__ float g_part[GATHER_BLOCKS];
__device__ unsigned g_ticket;

// ---------------- HMMA: m16n8k16 bf16 -> f32 ----------------
__device__ __forceinline__ void mma16816(float* d, const uint32_t* a, const uint32_t* b) {
    asm volatile(
        "mma.sync.aligned.m16n8k16.row.col.f32.bf16.bf16.f32 "
        "{%0,%1,%2,%3}, {%4,%5,%6,%7}, {%8,%9}, {%0,%1,%2,%3};"
        : "+f"(d[0]), "+f"(d[1]), "+f"(d[2]), "+f"(d[3])
        : "r"(a[0]), "r"(a[1]), "r"(a[2]), "r"(a[3]), "r"(b[0]), "r"(b[1]));
}

#define SROW 72      // bf16 row stride for A/B tiles (conflict-free fragment loads)
#define STG_STRIDE 80 // byte stride for fp8 half-tile staging (16B-aligned rows)

// fp8x2 -> half2 (low byte -> .x)
__device__ __forceinline__ __half2 c8(unsigned s) {
    __half2_raw r = __nv_cvt_fp8x2_to_halfraw2((__nv_fp8x2_storage_t)(s & 0xffffu),
                                               __NV_E4M3);
    return *reinterpret_cast<__half2*>(&r);
}
__device__ __forceinline__ unsigned short f2_to_e4m3x2(float x, float y) {
    return (unsigned short)__nv_cvt_float2_to_fp8x2(make_float2(x, y),
                                                    __NV_SATFINITE, __NV_E4M3);
}

// ---------------- kernel 1: HMMA precompute (split-N, reg-resident A frags) ----------------
// smem: [sA 18.4KB | sB 18.4KB], with the fp8 staging buffer (10KB) ALIASING sA
// (A fragments are hoisted to registers before the half-loop, so sA is dead).
// Total static smem 36.9KB -> 3 blocks/SM instead of 2.
__global__ __launch_bounds__(256) void prep_mma(
    const float* __restrict__ nci,
    const float* __restrict__ Mn,
    const float* __restrict__ Mm,
    const float* __restrict__ fmae,
    int nrows, int hBlocks, int f_rows)
{
    const int tid = threadIdx.x;
    const int lane = tid & 31;

    if (blockIdx.x >= hBlocks) {
        // ---- F -> e4m3 + row norms. 8 lanes per row. ----
        const int cb = blockIdx.x - hBlocks;
        const int gw = cb * 8 + (tid >> 5);
        const int grp = lane >> 3;
        const int sub = lane & 7;
        const int rowStride = CONV_BLOCKS * 8 * 4;
        for (int row = gw * 4 + grp; row < f_rows; row += rowStride) {
            const float4* src =
                reinterpret_cast<const float4*>(fmae + (size_t)row * 64 + sub * 8);
            float4 v0 = src[0];
            float4 v1 = src[1];
            float n = v0.x * v0.x;
            n = fmaf(v0.y, v0.y, n); n = fmaf(v0.z, v0.z, n); n = fmaf(v0.w, v0.w, n);
            n = fmaf(v1.x, v1.x, n); n = fmaf(v1.y, v1.y, n);
            n = fmaf(v1.z, v1.z, n); n = fmaf(v1.w, v1.w, n);
            unsigned p0 = f2_to_e4m3x2(v0.x, v0.y);
            unsigned p1 = f2_to_e4m3x2(v0.z, v0.w);
            unsigned p2 = f2_to_e4m3x2(v1.x, v1.y);
            unsigned p3 = f2_to_e4m3x2(v1.z, v1.w);
            uint2 o;
            o.x = p0 | (p1 << 16);
            o.y = p2 | (p3 << 16);
            *reinterpret_cast<uint2*>(g_Fb8 + (size_t)row * 64 + sub * 8) = o;
#pragma unroll
            for (int off = 1; off < 8; off <<= 1)
                n += __shfl_xor_sync(0xffffffffu, n, off);
            if (sub == 0) g_Nf[row] = n;
        }
        return;
    }

    __shared__ __align__(16) unsigned char smemRaw[2 * 128 * SROW * 2];   // 36.9 KB
    __nv_bfloat16 (*sA)[SROW] = reinterpret_cast<__nv_bfloat16(*)[SROW]>(smemRaw);
    __nv_bfloat16 (*sB)[SROW] =
        reinterpret_cast<__nv_bfloat16(*)[SROW]>(smemRaw + 128 * SROW * 2);
    unsigned char* sStg = smemRaw;   // aliases sA (safe: sA dead after frag hoist)

    const int w    = tid >> 5;
    const int gr   = lane >> 2;
    const int c    = lane & 3;
    const int rowBase = blockIdx.x * 128;

#pragma unroll
    for (int it = 0; it < 8; it++) {
        int idx = it * 256 + tid;
        int r = idx >> 4;
        int cq = idx & 15;
        int grow = rowBase + r;
        float4 v = (grow < nrows)
            ? reinterpret_cast<const float4*>(nci)[(size_t)grow * 16 + cq]
            : make_float4(0.f, 0.f, 0.f, 0.f);
        __nv_bfloat162 p0 = __floats2bfloat162_rn(v.x, v.y);
        __nv_bfloat162 p1 = __floats2bfloat162_rn(v.z, v.w);
        uint2 pk = make_uint2(*reinterpret_cast<uint32_t*>(&p0),
                              *reinterpret_cast<uint32_t*>(&p1));
        *reinterpret_cast<uint2*>(&sA[r][cq * 4]) = pk;
    }
#pragma unroll
    for (int it = 0; it < 8; it++) {
        int idx = it * 256 + tid;
        int r = idx >> 4;
        int cq = idx & 15;
        const float4* src = reinterpret_cast<const float4*>(r < 64 ? Mn : Mm);
        float4 v = src[(size_t)(r & 63) * 16 + cq];
        __nv_bfloat162 p0 = __floats2bfloat162_rn(v.x, v.y);
        __nv_bfloat162 p1 = __floats2bfloat162_rn(v.z, v.w);
        uint2 pk = make_uint2(*reinterpret_cast<uint32_t*>(&p0),
                              *reinterpret_cast<uint32_t*>(&p1));
        *reinterpret_cast<uint2*>(&sB[r][cq * 4]) = pk;
    }
    __syncthreads();

    // ---- hoist A fragments to registers (sA dead afterwards) ----
    uint32_t afr[4][4];
    {
        const int ar0 = w * 16 + gr;
#pragma unroll
        for (int kk = 0; kk < 4; kk++) {
            const int ak = kk * 16 + 2 * c;
            afr[kk][0] = *reinterpret_cast<const uint32_t*>(&sA[ar0][ak]);
            afr[kk][1] = *reinterpret_cast<const uint32_t*>(&sA[ar0 + 8][ak]);
            afr[kk][2] = *reinterpret_cast<const uint32_t*>(&sA[ar0][ak + 8]);
            afr[kk][3] = *reinterpret_cast<const uint32_t*>(&sA[ar0 + 8][ak + 8]);
        }
    }

#pragma unroll
    for (int half = 0; half < 2; half++) {
        float acc[8][4];
#pragma unroll
        for (int t = 0; t < 8; t++)
#pragma unroll
            for (int q = 0; q < 4; q++) acc[t][q] = 0.f;

#pragma unroll
        for (int kk = 0; kk < 4; kk++) {
            const int ak = kk * 16 + 2 * c;
#pragma unroll
            for (int t = 0; t < 8; t++) {
                uint32_t b[2];
                const int bn = (half * 8 + t) * 8 + gr;
                b[0] = *reinterpret_cast<const uint32_t*>(&sB[bn][ak]);
                b[1] = *reinterpret_cast<const uint32_t*>(&sB[bn][ak + 8]);
                mma16816(acc[t], afr[kk], b);
            }
        }

        // ---- row norms (f32-exact) for this half ----
        float n0 = 0.f, n1 = 0.f;
#pragma unroll
        for (int t = 0; t < 8; t++) {
            n0 = fmaf(acc[t][0], acc[t][0], n0); n0 = fmaf(acc[t][1], acc[t][1], n0);
            n1 = fmaf(acc[t][2], acc[t][2], n1); n1 = fmaf(acc[t][3], acc[t][3], n1);
        }
#pragma unroll
        for (int off = 1; off < 4; off <<= 1) {
            n0 += __shfl_xor_sync(0xffffffffu, n0, off);
            n1 += __shfl_xor_sync(0xffffffffu, n1, off);
        }
        const int gr0 = rowBase + w * 16 + gr;
        const int gr1 = gr0 + 8;
        float* ntab = half ? g_Nm : g_Nn;
        if (c == 0) {
            if (gr0 < nrows) ntab[gr0] = n0;
            if (gr1 < nrows) ntab[gr1] = n1;
        }

        // ---- fp8 epilogue for this half (sStg aliases sA region) ----
        __syncthreads();   // all frag loads & previous sStg consumers complete
        {
            const int r0 = w * 16 + gr;
#pragma unroll
            for (int t = 0; t < 8; t++) {
                int col = t * 8 + 2 * c;
                unsigned short v0 = f2_to_e4m3x2(acc[t][0], acc[t][1]);
                unsigned short v1 = f2_to_e4m3x2(acc[t][2], acc[t][3]);
                *reinterpret_cast<unsigned short*>(&sStg[r0 * STG_STRIDE + col]) = v0;
                *reinterpret_cast<unsigned short*>(&sStg[(r0 + 8) * STG_STRIDE + col]) = v1;
            }
        }
        __syncthreads();
        unsigned char* tab = half ? g_Hm8 : g_Hn8;
#pragma unroll
        for (int it = 0; it < 2; it++) {
            int idx = it * 256 + tid;
            int rr = idx >> 2;
            int ch = idx & 3;
            int grow = rowBase + rr;
            if (grow < nrows) {
                uint4 v = *reinterpret_cast<const uint4*>(
                    &sStg[rr * STG_STRIDE + ch * 16]);
                *reinterpret_cast<uint4*>(tab + (size_t)grow * 64 + ch * 16) = v;
            }
        }
    }
}

// ---------------- gather math: one sample's 16B chunk (uint4) per lane ----------------
__device__ __forceinline__ void cross_step(uint4 a, uint4 b, uint4 f,
                                           __half2& hacc0, __half2& hacc1) {
    __half2 s0 = __hadd2(c8(a.x), c8(b.x));
    __half2 s1 = __hadd2(c8(a.x >> 16), c8(b.x >> 16));
    __half2 s2 = __hadd2(c8(a.y), c8(b.y));
    __half2 s3 = __hadd2(c8(a.y >> 16), c8(b.y >> 16));
    hacc0 = __hfma2(s0, c8(f.x), hacc0);
    hacc1 = __hfma2(s1, c8(f.x >> 16), hacc1);
    hacc0 = __hfma2(s2, c8(f.y), hacc0);
    hacc1 = __hfma2(s3, c8(f.y >> 16), hacc1);
    __half2 s4 = __hadd2(c8(a.z), c8(b.z));
    __half2 s5 = __hadd2(c8(a.z >> 16), c8(b.z >> 16));
    __half2 s6 = __hadd2(c8(a.w), c8(b.w));
    __half2 s7 = __hadd2(c8(a.w >> 16), c8(b.w >> 16));
    hacc0 = __hfma2(s4, c8(f.z), hacc0);
    hacc1 = __hfma2(s5, c8(f.z >> 16), hacc1);
    hacc0 = __hfma2(s6, c8(f.w), hacc0);
    hacc1 = __hfma2(s7, c8(f.w >> 16), hacc1);
}

// ---------------- kernel 2: fp8 cross gather (4-lane groups) + norms + reduce ----------------
// (frozen at round-13 configuration: measured 33.9us)
__global__ __launch_bounds__(GATHER_TPB) void gather_cross(
    const int* __restrict__ pos_n,
    const int* __restrict__ pos_m,
    const int* __restrict__ pos_f,
    int B, float* __restrict__ out)
{
    const int lane = threadIdx.x & 31;
    const int wloc = threadIdx.x >> 5;
    const int warp = blockIdx.x * (GATHER_TPB >> 5) + wloc;
    const int nwarp = GATHER_BLOCKS * (GATHER_TPB >> 5);
    const int grp = lane >> 2;          // sample-group 0..7 within warp-step
    const int sub = lane & 3;           // 16B chunk within 64B row

    const char* bHn = reinterpret_cast<const char*>(g_Hn8) + sub * 16;
    const char* bHm = reinterpret_cast<const char*>(g_Hm8) + sub * 16;
    const char* bFb = reinterpret_cast<const char*>(g_Fb8) + sub * 16;

    float cross = 0.f;
    float normAcc = 0.f;

    const int perIter = nwarp * 32;
    const int nFull = B / perIter;

    for (int it = 0; it < nFull; it++) {
        const int base = it * perIter + warp * 32;
        const int i = base + lane;
        const int vn = pos_n[i];
        const int vm = pos_m[i];
        const int vf = pos_f[i];

        normAcc += g_Nn[vn] + g_Nm[vm] + 2.0f * g_Nf[vf];

        __half2 hacc0 = __float2half2_rn(0.f);
        __half2 hacc1 = __float2half2_rn(0.f);
#pragma unroll
        for (int t = 0; t < 4; t++) {
            const int s = t * 8 + grp;
            int an = __shfl_sync(0xffffffffu, vn, s);
            int am = __shfl_sync(0xffffffffu, vm, s);
            int af = __shfl_sync(0xffffffffu, vf, s);
            uint4 a = *reinterpret_cast<const uint4*>(bHn + an * 64);
            uint4 b = *reinterpret_cast<const uint4*>(bHm + am * 64);
            uint4 f = *reinterpret_cast<const uint4*>(bFb + af * 64);
            cross_step(a, b, f, hacc0, hacc1);
        }
        float2 fl0 = __half22float2(hacc0);
        float2 fl1 = __half22float2(hacc1);
        cross += (fl0.x + fl0.y) + (fl1.x + fl1.y);
    }

    // guarded tail (runs only if B is not a multiple of nwarp*32)
    for (int base = nFull * perIter + warp * 32; base < B; base += perIter) {
        const int i = base + lane;
        int vn = 0, vm = 0, vf = 0;
        if (i < B) {
            vn = pos_n[i]; vm = pos_m[i]; vf = pos_f[i];
            normAcc += g_Nn[vn] + g_Nm[vm] + 2.0f * g_Nf[vf];
        }
        const int cnt = (B - base < 32) ? (B - base) : 32;
        __half2 hacc0 = __float2half2_rn(0.f);
        __half2 hacc1 = __float2half2_rn(0.f);
#pragma unroll
        for (int t = 0; t < 4; t++) {
            const int s = t * 8 + grp;
            int an = __shfl_sync(0xffffffffu, vn, s);
            int am = __shfl_sync(0xffffffffu, vm, s);
            int af = __shfl_sync(0xffffffffu, vf, s);
            if (s < cnt) {
                uint4 a = *reinterpret_cast<const uint4*>(bHn + an * 64);
                uint4 b = *reinterpret_cast<const uint4*>(bHm + am * 64);
                uint4 f = *reinterpret_cast<const uint4*>(bFb + af * 64);
                cross_step(a, b, f, hacc0, hacc1);
            }
        }
        float2 fl0 = __half22float2(hacc0);
        float2 fl1 = __half22float2(hacc1);
        cross += (fl0.x + fl0.y) + (fl1.x + fl1.y);
    }

    float acc = normAcc - 2.f * cross;

#pragma unroll
    for (int off = 16; off > 0; off >>= 1)
        acc += __shfl_xor_sync(0xffffffffu, acc, off);

    __shared__ float ws[GATHER_TPB / 32];
    __shared__ bool isLast;
    if (lane == 0) ws[wloc] = acc;
    __syncthreads();
    if (threadIdx.x == 0) {
        float v = 0.f;
#pragma unroll
        for (int k = 0; k < GATHER_TPB / 32; k++) v += ws[k];
        g_part[blockIdx.x] = v;
        __threadfence();
        unsigned prev = atomicInc(&g_ticket, GATHER_BLOCKS - 1);
        isLast = (prev == GATHER_BLOCKS - 1);
    }
    __syncthreads();

    if (isLast) {
        float a = 0.0f;
        for (int i = threadIdx.x; i < GATHER_BLOCKS; i += GATHER_TPB)
            a += g_part[i];
#pragma unroll
        for (int off = 16; off > 0; off >>= 1)
            a += __shfl_xor_sync(0xffffffffu, a, off);
        if (lane == 0) ws[wloc] = a;
        __syncthreads();
        if (threadIdx.x == 0) {
            float v = 0.f;
#pragma unroll
            for (int k = 0; k < GATHER_TPB / 32; k++) v += ws[k];
            out[0] = v;
        }
    }
}

// ---------------- launch ----------------
extern "C" void kernel_launch(void* const* d_in, const int* in_sizes, int n_in,
                              void* d_out, int out_size)
{
    const int*   pos_n = (const int*)d_in[0];
    const int*   pos_m = (const int*)d_in[1];
    const int*   pos_f = (const int*)d_in[2];
    const float* nci   = (const float*)d_in[3];
    const float* fmae  = (const float*)d_in[4];
    const float* Mn    = (const float*)d_in[5];
    const float* Mm    = (const float*)d_in[6];

    int B = in_sizes[0];
    int nci_rows = in_sizes[3] / DIM;
    if (nci_rows > NCI_MAX) nci_rows = NCI_MAX;
    int f_rows = in_sizes[4] / DIM;
    if (f_rows > FMA_MAX) f_rows = FMA_MAX;

    // allow max smem carveout so 3 blocks/SM fit (hint; harmless if ignored)
    cudaFuncSetAttribute(prep_mma,
                         cudaFuncAttributePreferredSharedMemoryCarveout, 100);

    int hBlocks = (nci_rows + 127) / 128;
    prep_mma<<<hBlocks + CONV_BLOCKS, 256>>>(
        nci, Mn, Mm, fmae, nci_rows, hBlocks, f_rows);
    gather_cross<<<GATHER_BLOCKS, GATHER_TPB>>>(pos_n, pos_m, pos_f,
                                                B, (float*)d_out);
}

// round 15
// speedup vs baseline: 1.5250x; 1.5250x over previous
#include <cuda_runtime.h>
#include <cuda_bf16.h>
#include <cuda_fp16.h>
#include <cuda_fp8.h>
#include <cstdint>

#define DIM 64
#define NCI_MAX 150000
#define FMA_MAX 100000
#define GATHER_BLOCKS 2048
#define GATHER_TPB 256
#define CONV_BLOCKS 512

// ---------------- scratch (device globals: allocation-free rule) ----------------
__device__ __align__(128) unsigned char g_Hn8[NCI_MAX * DIM];   // e4m3, 9.6 MB
__device__ __align__(128) unsigned char g_Hm8[NCI_MAX * DIM];   // e4m3, 9.6 MB
__device__ __align__(128) unsigned char g_Fb8[FMA_MAX * DIM];   // e4m3, 6.4 MB
__device__ float g_Nn[NCI_MAX];       // row norms |Hn_r|^2 (f32-exact)
__device__ float g_Nm[NCI_MAX];
__device__ float g_Nf[FMA_MAX];
__device__ float g_part[GATHER_BLOCKS];
__device__ unsigned g_ticket;

// ---------------- HMMA: m16n8k16 bf16 -> f32 ----------------
__device__ __forceinline__ void mma16816(float* d, const uint32_t* a, const uint32_t* b) {
    asm volatile(
        "mma.sync.aligned.m16n8k16.row.col.f32.bf16.bf16.f32 "
        "{%0,%1,%2,%3}, {%4,%5,%6,%7}, {%8,%9}, {%0,%1,%2,%3};"
        : "+f"(d[0]), "+f"(d[1]), "+f"(d[2]), "+f"(d[3])
        : "r"(a[0]), "r"(a[1]), "r"(a[2]), "r"(a[3]), "r"(b[0]), "r"(b[1]));
}

#define SROW 72      // bf16 row stride for A/B tiles (conflict-free fragment loads)
#define STG_STRIDE 80 // byte stride for fp8 half-tile staging (16B-aligned rows)

// fp8x2 -> half2 (low byte -> .x)
__device__ __forceinline__ __half2 c8(unsigned s) {
    __half2_raw r = __nv_cvt_fp8x2_to_halfraw2((__nv_fp8x2_storage_t)(s & 0xffffu),
                                               __NV_E4M3);
    return *reinterpret_cast<__half2*>(&r);
}
__device__ __forceinline__ unsigned short f2_to_e4m3x2(float x, float y) {
    return (unsigned short)__nv_cvt_float2_to_fp8x2(make_float2(x, y),
                                                    __NV_SATFINITE, __NV_E4M3);
}

// ---------------- kernel 1: HMMA precompute (split-N) + norms + F convert ----------------
__global__ __launch_bounds__(256) void prep_mma(
    const float* __restrict__ nci,
    const float* __restrict__ Mn,
    const float* __restrict__ Mm,
    const float* __restrict__ fmae,
    int nrows, int hBlocks, int f_rows)
{
    const int tid = threadIdx.x;
    const int lane = tid & 31;

    if (blockIdx.x >= hBlocks) {
        // ---- F -> e4m3 + row norms. 8 lanes per row. ----
        const int cb = blockIdx.x - hBlocks;
        const int gw = cb * 8 + (tid >> 5);
        const int grp = lane >> 3;
        const int sub = lane & 7;
        const int rowStride = CONV_BLOCKS * 8 * 4;
        for (int row = gw * 4 + grp; row < f_rows; row += rowStride) {
            const float4* src =
                reinterpret_cast<const float4*>(fmae + (size_t)row * 64 + sub * 8);
            float4 v0 = src[0];
            float4 v1 = src[1];
            float n = v0.x * v0.x;
            n = fmaf(v0.y, v0.y, n); n = fmaf(v0.z, v0.z, n); n = fmaf(v0.w, v0.w, n);
            n = fmaf(v1.x, v1.x, n); n = fmaf(v1.y, v1.y, n);
            n = fmaf(v1.z, v1.z, n); n = fmaf(v1.w, v1.w, n);
            unsigned p0 = f2_to_e4m3x2(v0.x, v0.y);
            unsigned p1 = f2_to_e4m3x2(v0.z, v0.w);
            unsigned p2 = f2_to_e4m3x2(v1.x, v1.y);
            unsigned p3 = f2_to_e4m3x2(v1.z, v1.w);
            uint2 o;
            o.x = p0 | (p1 << 16);
            o.y = p2 | (p3 << 16);
            *reinterpret_cast<uint2*>(g_Fb8 + (size_t)row * 64 + sub * 8) = o;
#pragma unroll
            for (int off = 1; off < 8; off <<= 1)
                n += __shfl_xor_sync(0xffffffffu, n, off);
            if (sub == 0) g_Nf[row] = n;
        }
        return;
    }

    // ---- matmul tile: D[128x128] = E[128x64] @ [Mn;Mm]^T, two 64-col halves ----
    __shared__ __align__(16) __nv_bfloat16 sA[128][SROW];
    __shared__ __align__(16) __nv_bfloat16 sB[128][SROW];
    __shared__ __align__(16) unsigned char sStg[128 * STG_STRIDE];

    const int w    = tid >> 5;
    const int gr   = lane >> 2;
    const int c    = lane & 3;
    const int rowBase = blockIdx.x * 128;

#pragma unroll
    for (int it = 0; it < 8; it++) {
        int idx = it * 256 + tid;
        int r = idx >> 4;
        int cq = idx & 15;
        int grow = rowBase + r;
        float4 v = (grow < nrows)
            ? reinterpret_cast<const float4*>(nci)[(size_t)grow * 16 + cq]
            : make_float4(0.f, 0.f, 0.f, 0.f);
        __nv_bfloat162 p0 = __floats2bfloat162_rn(v.x, v.y);
        __nv_bfloat162 p1 = __floats2bfloat162_rn(v.z, v.w);
        uint2 pk = make_uint2(*reinterpret_cast<uint32_t*>(&p0),
                              *reinterpret_cast<uint32_t*>(&p1));
        *reinterpret_cast<uint2*>(&sA[r][cq * 4]) = pk;
    }
#pragma unroll
    for (int it = 0; it < 8; it++) {
        int idx = it * 256 + tid;
        int r = idx >> 4;
        int cq = idx & 15;
        const float4* src = reinterpret_cast<const float4*>(r < 64 ? Mn : Mm);
        float4 v = src[(size_t)(r & 63) * 16 + cq];
        __nv_bfloat162 p0 = __floats2bfloat162_rn(v.x, v.y);
        __nv_bfloat162 p1 = __floats2bfloat162_rn(v.z, v.w);
        uint2 pk = make_uint2(*reinterpret_cast<uint32_t*>(&p0),
                              *reinterpret_cast<uint32_t*>(&p1));
        *reinterpret_cast<uint2*>(&sB[r][cq * 4]) = pk;
    }
    __syncthreads();

#pragma unroll
    for (int half = 0; half < 2; half++) {
        float acc[8][4];
#pragma unroll
        for (int t = 0; t < 8; t++)
#pragma unroll
            for (int q = 0; q < 4; q++) acc[t][q] = 0.f;

#pragma unroll
        for (int kk = 0; kk < 4; kk++) {
            uint32_t a[4];
            const int ar0 = w * 16 + gr;
            const int ak  = kk * 16 + 2 * c;
            a[0] = *reinterpret_cast<const uint32_t*>(&sA[ar0][ak]);
            a[1] = *reinterpret_cast<const uint32_t*>(&sA[ar0 + 8][ak]);
            a[2] = *reinterpret_cast<const uint32_t*>(&sA[ar0][ak + 8]);
            a[3] = *reinterpret_cast<const uint32_t*>(&sA[ar0 + 8][ak + 8]);
#pragma unroll
            for (int t = 0; t < 8; t++) {
                uint32_t b[2];
                const int bn = (half * 8 + t) * 8 + gr;
                b[0] = *reinterpret_cast<const uint32_t*>(&sB[bn][ak]);
                b[1] = *reinterpret_cast<const uint32_t*>(&sB[bn][ak + 8]);
                mma16816(acc[t], a, b);
            }
        }

        // ---- row norms (f32-exact) for this half ----
        float n0 = 0.f, n1 = 0.f;
#pragma unroll
        for (int t = 0; t < 8; t++) {
            n0 = fmaf(acc[t][0], acc[t][0], n0); n0 = fmaf(acc[t][1], acc[t][1], n0);
            n1 = fmaf(acc[t][2], acc[t][2], n1); n1 = fmaf(acc[t][3], acc[t][3], n1);
        }
#pragma unroll
        for (int off = 1; off < 4; off <<= 1) {
            n0 += __shfl_xor_sync(0xffffffffu, n0, off);
            n1 += __shfl_xor_sync(0xffffffffu, n1, off);
        }
        const int gr0 = rowBase + w * 16 + gr;
        const int gr1 = gr0 + 8;
        float* ntab = half ? g_Nm : g_Nn;
        if (c == 0) {
            if (gr0 < nrows) ntab[gr0] = n0;
            if (gr1 < nrows) ntab[gr1] = n1;
        }

        // ---- fp8 epilogue for this half ----
        __syncthreads();
        {
            const int r0 = w * 16 + gr;
#pragma unroll
            for (int t = 0; t < 8; t++) {
                int col = t * 8 + 2 * c;
                unsigned short v0 = f2_to_e4m3x2(acc[t][0], acc[t][1]);
                unsigned short v1 = f2_to_e4m3x2(acc[t][2], acc[t][3]);
                *reinterpret_cast<unsigned short*>(&sStg[r0 * STG_STRIDE + col]) = v0;
                *reinterpret_cast<unsigned short*>(&sStg[(r0 + 8) * STG_STRIDE + col]) = v1;
            }
        }
        __syncthreads();
        unsigned char* tab = half ? g_Hm8 : g_Hn8;
#pragma unroll
        for (int it = 0; it < 2; it++) {
            int idx = it * 256 + tid;
            int rr = idx >> 2;
            int ch = idx & 3;
            int grow = rowBase + rr;
            if (grow < nrows) {
                uint4 v = *reinterpret_cast<const uint4*>(
                    &sStg[rr * STG_STRIDE + ch * 16]);
                *reinterpret_cast<uint4*>(tab + (size_t)grow * 64 + ch * 16) = v;
            }
        }
    }
}

// ---------------- gather math: one sample's 16B chunk (uint4) per lane ----------------
__device__ __forceinline__ void cross_step(uint4 a, uint4 b, uint4 f,
                                           __half2& hacc0, __half2& hacc1) {
    __half2 s0 = __hadd2(c8(a.x), c8(b.x));
    __half2 s1 = __hadd2(c8(a.x >> 16), c8(b.x >> 16));
    __half2 s2 = __hadd2(c8(a.y), c8(b.y));
    __half2 s3 = __hadd2(c8(a.y >> 16), c8(b.y >> 16));
    hacc0 = __hfma2(s0, c8(f.x), hacc0);
    hacc1 = __hfma2(s1, c8(f.x >> 16), hacc1);
    hacc0 = __hfma2(s2, c8(f.y), hacc0);
    hacc1 = __hfma2(s3, c8(f.y >> 16), hacc1);
    __half2 s4 = __hadd2(c8(a.z), c8(b.z));
    __half2 s5 = __hadd2(c8(a.z >> 16), c8(b.z >> 16));
    __half2 s6 = __hadd2(c8(a.w), c8(b.w));
    __half2 s7 = __hadd2(c8(a.w >> 16), c8(b.w >> 16));
    hacc0 = __hfma2(s4, c8(f.z), hacc0);
    hacc1 = __hfma2(s5, c8(f.z >> 16), hacc1);
    hacc0 = __hfma2(s6, c8(f.w), hacc0);
    hacc1 = __hfma2(s7, c8(f.w >> 16), hacc1);
}

// ---------------- kernel 2: fp8 cross gather (4-lane groups) + norms + reduce ----------------
// loss = sum_i [ Nn[vn] + Nm[vm] + 2*Nf[vf] ] - 2 * sum_i (hn+hm).f
__global__ __launch_bounds__(GATHER_TPB) void gather_cross(
    const int* __restrict__ pos_n,
    const int* __restrict__ pos_m,
    const int* __restrict__ pos_f,
    int B, float* __restrict__ out)
{
    const int lane = threadIdx.x & 31;
    const int wloc = threadIdx.x >> 5;
    const int warp = blockIdx.x * (GATHER_TPB >> 5) + wloc;
    const int nwarp = GATHER_BLOCKS * (GATHER_TPB >> 5);
    const int grp = lane >> 2;          // sample-group 0..7 within warp-step
    const int sub = lane & 3;           // 16B chunk within 64B row

    const char* bHn = reinterpret_cast<const char*>(g_Hn8) + sub * 16;
    const char* bHm = reinterpret_cast<const char*>(g_Hm8) + sub * 16;
    const char* bFb = reinterpret_cast<const char*>(g_Fb8) + sub * 16;

    float cross = 0.f;
    float normAcc = 0.f;

    const int perIter = nwarp * 32;
    const int nFull = B / perIter;

    for (int it = 0; it < nFull; it++) {
        const int base = it * perIter + warp * 32;
        const int i = base + lane;
        const int vn = pos_n[i];
        const int vm = pos_m[i];
        const int vf = pos_f[i];

        normAcc += g_Nn[vn] + g_Nm[vm] + 2.0f * g_Nf[vf];

        __half2 hacc0 = __float2half2_rn(0.f);
        __half2 hacc1 = __float2half2_rn(0.f);
#pragma unroll
        for (int t = 0; t < 4; t++) {
            const int s = t * 8 + grp;
            int an = __shfl_sync(0xffffffffu, vn, s);
            int am = __shfl_sync(0xffffffffu, vm, s);
            int af = __shfl_sync(0xffffffffu, vf, s);
            uint4 a = *reinterpret_cast<const uint4*>(bHn + an * 64);
            uint4 b = *reinterpret_cast<const uint4*>(bHm + am * 64);
            uint4 f = *reinterpret_cast<const uint4*>(bFb + af * 64);
            cross_step(a, b, f, hacc0, hacc1);
        }
        float2 fl0 = __half22float2(hacc0);
        float2 fl1 = __half22float2(hacc1);
        cross += (fl0.x + fl0.y) + (fl1.x + fl1.y);
    }

    // guarded tail (runs only if B is not a multiple of nwarp*32)
    for (int base = nFull * perIter + warp * 32; base < B; base += perIter) {
        const int i = base + lane;
        int vn = 0, vm = 0, vf = 0;
        if (i < B) {
            vn = pos_n[i]; vm = pos_m[i]; vf = pos_f[i];
            normAcc += g_Nn[vn] + g_Nm[vm] + 2.0f * g_Nf[vf];
        }
        const int cnt = (B - base < 32) ? (B - base) : 32;
        __half2 hacc0 = __float2half2_rn(0.f);
        __half2 hacc1 = __float2half2_rn(0.f);
#pragma unroll
        for (int t = 0; t < 4; t++) {
            const int s = t * 8 + grp;
            int an = __shfl_sync(0xffffffffu, vn, s);
            int am = __shfl_sync(0xffffffffu, vm, s);
            int af = __shfl_sync(0xffffffffu, vf, s);
            if (s < cnt) {
                uint4 a = *reinterpret_cast<const uint4*>(bHn + an * 64);
                uint4 b = *reinterpret_cast<const uint4*>(bHm + am * 64);
                uint4 f = *reinterpret_cast<const uint4*>(bFb + af * 64);
                cross_step(a, b, f, hacc0, hacc1);
            }
        }
        float2 fl0 = __half22float2(hacc0);
        float2 fl1 = __half22float2(hacc1);
        cross += (fl0.x + fl0.y) + (fl1.x + fl1.y);
    }

    float acc = normAcc - 2.f * cross;

#pragma unroll
    for (int off = 16; off > 0; off >>= 1)
        acc += __shfl_xor_sync(0xffffffffu, acc, off);

    __shared__ float ws[GATHER_TPB / 32];
    __shared__ bool isLast;
    if (lane == 0) ws[wloc] = acc;
    __syncthreads();
    if (threadIdx.x == 0) {
        float v = 0.f;
#pragma unroll
        for (int k = 0; k < GATHER_TPB / 32; k++) v += ws[k];
        g_part[blockIdx.x] = v;
        __threadfence();
        unsigned prev = atomicInc(&g_ticket, GATHER_BLOCKS - 1);
        isLast = (prev == GATHER_BLOCKS - 1);
    }
    __syncthreads();

    if (isLast) {
        float a = 0.0f;
        for (int i = threadIdx.x; i < GATHER_BLOCKS; i += GATHER_TPB)
            a += g_part[i];
#pragma unroll
        for (int off = 16; off > 0; off >>= 1)
            a += __shfl_xor_sync(0xffffffffu, a, off);
        if (lane == 0) ws[wloc] = a;
        __syncthreads();
        if (threadIdx.x == 0) {
            float v = 0.f;
#pragma unroll
            for (int k = 0; k < GATHER_TPB / 32; k++) v += ws[k];
            out[0] = v;
        }
    }
}

// ---------------- launch ----------------
extern "C" void kernel_launch(void* const* d_in, const int* in_sizes, int n_in,
                              void* d_out, int out_size)
{
    const int*   pos_n = (const int*)d_in[0];
    const int*   pos_m = (const int*)d_in[1];
    const int*   pos_f = (const int*)d_in[2];
    const float* nci   = (const float*)d_in[3];
    const float* fmae  = (const float*)d_in[4];
    const float* Mn    = (const float*)d_in[5];
    const float* Mm    = (const float*)d_in[6];

    int B = in_sizes[0];
    int nci_rows = in_sizes[3] / DIM;
    if (nci_rows > NCI_MAX) nci_rows = NCI_MAX;
    int f_rows = in_sizes[4] / DIM;
    if (f_rows > FMA_MAX) f_rows = FMA_MAX;

    int hBlocks = (nci_rows + 127) / 128;
    prep_mma<<<hBlocks + CONV_BLOCKS, 256>>>(
        nci, Mn, Mm, fmae, nci_rows, hBlocks, f_rows);
    gather_cross<<<GATHER_BLOCKS, GATHER_TPB>>>(pos_n, pos_m, pos_f,
                                                B, (float*)d_out);
}